// round 3
// baseline (speedup 1.0000x reference)
#include <cuda_runtime.h>
#include <math.h>
#include <stdint.h>

// Problem constants
#define Bdim   2
#define Sdim   2048
#define Edim   2048
#define Hdim   16
#define HKVdim 4
#define Ddim   128
#define KQVdim 2048
#define KVdim  512            // HKV * D — also the compact Q / attn-out width
#define WIN    256
#define Mrows  (Bdim * Sdim)  // 4096

// Scratch (static __device__ — no allocation allowed)
__device__ float g_q [(size_t)Mrows * KVdim];    // compact Q: only heads 0..3 used
__device__ float g_k [(size_t)Mrows * KVdim];
__device__ float g_v [(size_t)Mrows * KVdim];
__device__ float g_ao[(size_t)Mrows * KVdim];    // compact attn out (4 distinct heads)
__device__ float g_wf[(size_t)Edim  * KVdim];    // folded Wo

// ---------------------------------------------------------------------------
// GEMM: Y[M,N] = X[M,K] @ W[N,K]^T (+ bias[N] if bias != nullptr)
// BM=128, BN=128, BK=16, 256 threads, 8x8 microtile per thread.
// ---------------------------------------------------------------------------
#define BM 128
#define BN 128
#define BK 16

__global__ void __launch_bounds__(256, 1)
gemm_xwt(const float* __restrict__ X, const float* __restrict__ W,
         const float* __restrict__ bias, float* __restrict__ Y,
         int M, int N, int K)
{
    __shared__ float As[BK][BM + 4];
    __shared__ float Bs[BK][BN + 4];

    const int tid = threadIdx.x;
    const int tx  = tid & 15;
    const int ty  = tid >> 4;
    const int bm  = blockIdx.y * BM;
    const int bn  = blockIdx.x * BN;

    float acc[8][8];
    #pragma unroll
    for (int i = 0; i < 8; i++)
        #pragma unroll
        for (int j = 0; j < 8; j++) acc[i][j] = 0.0f;

    for (int k0 = 0; k0 < K; k0 += BK) {
        #pragma unroll
        for (int p = 0; p < 2; p++) {
            int idx = p * 256 + tid;      // 0..511
            int row = idx >> 2;
            int kv  = idx & 3;
            float4 a = *reinterpret_cast<const float4*>(
                &X[(size_t)(bm + row) * K + k0 + kv * 4]);
            As[kv*4+0][row] = a.x; As[kv*4+1][row] = a.y;
            As[kv*4+2][row] = a.z; As[kv*4+3][row] = a.w;
            float4 b = *reinterpret_cast<const float4*>(
                &W[(size_t)(bn + row) * K + k0 + kv * 4]);
            Bs[kv*4+0][row] = b.x; Bs[kv*4+1][row] = b.y;
            Bs[kv*4+2][row] = b.z; Bs[kv*4+3][row] = b.w;
        }
        __syncthreads();

        #pragma unroll
        for (int kk = 0; kk < BK; kk++) {
            float a[8], b[8];
            #pragma unroll
            for (int i = 0; i < 8; i++) a[i] = As[kk][ty * 8 + i];
            #pragma unroll
            for (int j = 0; j < 8; j++) b[j] = Bs[kk][tx * 8 + j];
            #pragma unroll
            for (int i = 0; i < 8; i++)
                #pragma unroll
                for (int j = 0; j < 8; j++)
                    acc[i][j] = fmaf(a[i], b[j], acc[i][j]);
        }
        __syncthreads();
    }

    #pragma unroll
    for (int i = 0; i < 8; i++) {
        int row = bm + ty * 8 + i;
        #pragma unroll
        for (int j = 0; j < 8; j++) {
            int col = bn + tx * 8 + j;
            float v = acc[i][j];
            if (bias) v += bias[col];
            Y[(size_t)row * N + col] = v;
        }
    }
}

// ---------------------------------------------------------------------------
// Fold Wo: Wf[e, g*D+d] = sum_{u=0..3} Wo[e, (4g+u)*D + d]
// ---------------------------------------------------------------------------
__global__ void fold_wo(const float* __restrict__ Wo, float* __restrict__ Wf)
{
    int i = blockIdx.x * blockDim.x + threadIdx.x;  // over E*KVdim
    if (i >= Edim * KVdim) return;
    int e = i / KVdim;
    int c = i % KVdim;
    int g = c / Ddim, d = c % Ddim;
    float s = 0.0f;
    #pragma unroll
    for (int u = 0; u < 4; u++)
        s += Wo[(size_t)e * KQVdim + (size_t)(g * 4 + u) * Ddim + d];
    Wf[i] = s;
}

// ---------------------------------------------------------------------------
// Sliding-window GQA attention (flash-style online softmax).
// Only HKV=4 distinct heads (reference uses q[:, h//4]!).
// grid: (S/32, B*HKV); block: 256 threads (8 warps, 4 query rows per warp).
// q,k,v,out: [B,S,HKV*D] compact.
// ---------------------------------------------------------------------------
__global__ void __launch_bounds__(256, 2)
attn_window(const float* __restrict__ q, const float* __restrict__ k,
            const float* __restrict__ v, float* __restrict__ out)
{
    __shared__ float Qs[32][Ddim];
    __shared__ float Ks[Ddim][33];   // transposed, +1 pad
    __shared__ float Vs[32][Ddim];

    const int tid  = threadIdx.x;
    const int warp = tid >> 5;
    const int lane = tid & 31;

    const int bh  = blockIdx.y;               // 0..B*HKV-1
    const int b   = bh / HKVdim;
    const int kvh = bh % HKVdim;
    const int q0  = blockIdx.x * 32;

    const float* qptr = q + ((size_t)b * Sdim + q0) * KVdim + kvh * Ddim;

    #pragma unroll
    for (int e = 0; e < 16; e++) {
        int lin = e * 256 + tid;
        int r = lin >> 7, d = lin & 127;
        Qs[r][d] = qptr[(size_t)r * KVdim + d];
    }

    float m[4], l[4], O[4][4];
    #pragma unroll
    for (int r = 0; r < 4; r++) {
        m[r] = -1e30f; l[r] = 0.0f;
        #pragma unroll
        for (int c = 0; c < 4; c++) O[r][c] = 0.0f;
    }

    int ktlo = q0 - (WIN - 1);
    if (ktlo < 0) ktlo = 0;
    ktlo = (ktlo / 32) * 32;

    for (int k0 = ktlo; k0 <= q0; k0 += 32) {
        const float* kptr = k + ((size_t)b * Sdim + k0) * KVdim + kvh * Ddim;
        const float* vptr = v + ((size_t)b * Sdim + k0) * KVdim + kvh * Ddim;
        __syncthreads();
        #pragma unroll
        for (int e = 0; e < 16; e++) {
            int lin = e * 256 + tid;
            int j = lin >> 7, d = lin & 127;
            Ks[d][j] = kptr[(size_t)j * KVdim + d];
            Vs[j][d] = vptr[(size_t)j * KVdim + d];
        }
        __syncthreads();

        #pragma unroll
        for (int r = 0; r < 4; r++) {
            const int row = warp * 4 + r;
            const int i   = q0 + row;
            const int jg  = k0 + lane;

            float s = 0.0f;
            #pragma unroll
            for (int d = 0; d < Ddim; d++)
                s = fmaf(Qs[row][d], Ks[d][lane], s);

            const bool valid = (jg <= i) && (jg > i - WIN);
            s = valid ? s : -1e30f;

            float mt = s;
            #pragma unroll
            for (int off = 16; off; off >>= 1)
                mt = fmaxf(mt, __shfl_xor_sync(0xffffffffu, mt, off));
            const float mnew  = fmaxf(m[r], mt);
            const float p     = valid ? __expf(s - mnew) : 0.0f;
            const float alpha = __expf(m[r] - mnew);
            m[r] = mnew;

            float rs = p;
            #pragma unroll
            for (int off = 16; off; off >>= 1)
                rs += __shfl_xor_sync(0xffffffffu, rs, off);
            l[r] = l[r] * alpha + rs;

            #pragma unroll
            for (int c = 0; c < 4; c++) O[r][c] *= alpha;
            #pragma unroll
            for (int j = 0; j < 32; j++) {
                const float pj = __shfl_sync(0xffffffffu, p, j);
                #pragma unroll
                for (int c = 0; c < 4; c++)
                    O[r][c] = fmaf(pj, Vs[j][c * 32 + lane], O[r][c]);
            }
        }
    }

    float* optr = out + ((size_t)b * Sdim + q0) * KVdim + kvh * Ddim;
    #pragma unroll
    for (int r = 0; r < 4; r++) {
        const int row = warp * 4 + r;
        const float inv = 1.0f / l[r];
        #pragma unroll
        for (int c = 0; c < 4; c++)
            optr[(size_t)row * KVdim + c * 32 + lane] = O[r][c] * inv;
    }
}

// ---------------------------------------------------------------------------
// Launch
// ---------------------------------------------------------------------------
extern "C" void kernel_launch(void* const* d_in, const int* in_sizes, int n_in,
                              void* d_out, int out_size)
{
    const float* x  = (const float*)d_in[0];   // hidden_states [B,S,E]
    const float* Wq = (const float*)d_in[1];   // [KQV,E] — only rows 0..511 used
    const float* Wk = (const float*)d_in[2];   // [KV_DIM,E]
    const float* Wv = (const float*)d_in[3];   // [KV_DIM,E]
    const float* Wo = (const float*)d_in[4];   // [E,KQV]
    const float* bo = (const float*)d_in[5];   // [E]
    float* out = (float*)d_out;

    float *qb, *kb, *vb, *ab, *wf;
    cudaGetSymbolAddress((void**)&qb, g_q);
    cudaGetSymbolAddress((void**)&kb, g_k);
    cudaGetSymbolAddress((void**)&vb, g_v);
    cudaGetSymbolAddress((void**)&ab, g_ao);
    cudaGetSymbolAddress((void**)&wf, g_wf);

    // Fold Wo (independent of other work; serialized on stream anyway)
    fold_wo<<<(Edim * KVdim + 255) / 256, 256>>>(Wo, wf);

    // Q projection: only q-heads 0..3 are ever used by the reference
    gemm_xwt<<<dim3(KVdim / BN, Mrows / BM), 256>>>(x, Wq, nullptr, qb,
                                                    Mrows, KVdim, Edim);
    gemm_xwt<<<dim3(KVdim / BN, Mrows / BM), 256>>>(x, Wk, nullptr, kb,
                                                    Mrows, KVdim, Edim);
    gemm_xwt<<<dim3(KVdim / BN, Mrows / BM), 256>>>(x, Wv, nullptr, vb,
                                                    Mrows, KVdim, Edim);

    // Sliding-window attention over 4 distinct kv heads
    attn_window<<<dim3(Sdim / 32, Bdim * HKVdim), 256>>>(qb, kb, vb, ab);

    // Output projection with folded Wo + bias
    gemm_xwt<<<dim3(Edim / BN, Mrows / BM), 256>>>(ab, wf, bo, out,
                                                   Mrows, Edim, KVdim);
}

// round 5
// speedup vs baseline: 1.3607x; 1.3607x over previous
#include <cuda_runtime.h>
#include <math.h>
#include <stdint.h>

// Problem constants
#define Bdim   2
#define Sdim   2048
#define Edim   2048
#define Hdim   16
#define HKVdim 4
#define Ddim   128
#define KQVdim 2048
#define KVdim  512            // HKV * D — compact Q / attn-out width
#define WIN    256
#define Mrows  (Bdim * Sdim)  // 4096

// Scratch (static __device__ — no allocation allowed)
__device__ float g_q [(size_t)Mrows * KVdim];
__device__ float g_k [(size_t)Mrows * KVdim];
__device__ float g_v [(size_t)Mrows * KVdim];
__device__ float g_ao[(size_t)Mrows * KVdim];
__device__ float g_wf[(size_t)Edim  * KVdim];    // folded Wo

// ---------------------------------------------------------------------------
// 3xTF32 tensor-core GEMM (fp32-accurate): Y[M,N] = X[M,K] @ W[N,K]^T (+bias)
// BM=128, BN=128, BK=16, 256 threads (8 warps, 2x4), 64x32 per warp.
// smem holds fp32; hi/lo TF32 split at fragment load.
// acc += Alo*Bhi + Ahi*Blo + Ahi*Bhi  (3 MMAs per tile-pair)
// ---------------------------------------------------------------------------
#define BM 128
#define BN 128
#define BK 16
#define MSTR (BM + 4)   // 132 floats stride

__device__ __forceinline__ uint32_t f2tf32(float f) {
    uint32_t r;
    asm("cvt.rna.tf32.f32 %0, %1;" : "=r"(r) : "f"(f));
    return r;
}

__device__ __forceinline__ void split_tf32(float f, uint32_t& hi, uint32_t& lo) {
    hi = f2tf32(f);
    lo = f2tf32(f - __uint_as_float(hi));
}

__device__ __forceinline__ void mma_tf32(float c[4], uint32_t a0, uint32_t a1,
                                         uint32_t a2, uint32_t a3,
                                         uint32_t b0, uint32_t b1) {
    asm volatile(
        "mma.sync.aligned.m16n8k8.row.col.f32.tf32.tf32.f32 "
        "{%0,%1,%2,%3}, {%4,%5,%6,%7}, {%8,%9}, {%0,%1,%2,%3};"
        : "+f"(c[0]), "+f"(c[1]), "+f"(c[2]), "+f"(c[3])
        : "r"(a0), "r"(a1), "r"(a2), "r"(a3), "r"(b0), "r"(b1));
}

__global__ void __launch_bounds__(256, 1)
gemm_3xtf32(const float* __restrict__ X, const float* __restrict__ W,
            const float* __restrict__ bias, float* __restrict__ Y,
            int M, int N, int K)
{
    __shared__ float As[2][BK][MSTR];
    __shared__ float Bs[2][BK][MSTR];

    const int tid  = threadIdx.x;
    const int warp = tid >> 5;
    const int lane = tid & 31;
    const int g    = lane >> 2;        // group 0..7
    const int tg   = lane & 3;         // thread-in-group 0..3
    const int wm   = warp & 1;         // 0..1  (64 rows each)
    const int wn   = warp >> 1;        // 0..3  (32 cols each)
    const int bm   = blockIdx.y * BM;
    const int bn   = blockIdx.x * BN;

    const int ldrow0 = tid >> 2;       // rows 0..63 (p=0), +64 (p=1)
    const int ldkv   = tid & 3;

    float acc[4][4][4];
    #pragma unroll
    for (int i = 0; i < 4; i++)
        #pragma unroll
        for (int j = 0; j < 4; j++)
            #pragma unroll
            for (int c = 0; c < 4; c++) acc[i][j][c] = 0.0f;

    const int T = K / BK;

    // Prologue: tile 0 -> buffer 0
    #pragma unroll
    for (int p = 0; p < 2; p++) {
        int row = ldrow0 + p * 64;
        float4 a = *reinterpret_cast<const float4*>(&X[(size_t)(bm + row) * K + ldkv * 4]);
        As[0][ldkv*4+0][row] = a.x; As[0][ldkv*4+1][row] = a.y;
        As[0][ldkv*4+2][row] = a.z; As[0][ldkv*4+3][row] = a.w;
        float4 b = *reinterpret_cast<const float4*>(&W[(size_t)(bn + row) * K + ldkv * 4]);
        Bs[0][ldkv*4+0][row] = b.x; Bs[0][ldkv*4+1][row] = b.y;
        Bs[0][ldkv*4+2][row] = b.z; Bs[0][ldkv*4+3][row] = b.w;
    }
    __syncthreads();

    for (int t = 0; t < T; t++) {
        const int cur = t & 1;
        const int nxt = cur ^ 1;

        // Prefetch next tile into registers (overlaps with MMA below)
        float4 pa[2], pb[2];
        if (t + 1 < T) {
            const int k0 = (t + 1) * BK;
            #pragma unroll
            for (int p = 0; p < 2; p++) {
                int row = ldrow0 + p * 64;
                pa[p] = *reinterpret_cast<const float4*>(&X[(size_t)(bm + row) * K + k0 + ldkv * 4]);
                pb[p] = *reinterpret_cast<const float4*>(&W[(size_t)(bn + row) * K + k0 + ldkv * 4]);
            }
        }

        // Compute: 2 k-steps of 8, 3xTF32 per fragment pair
        #pragma unroll
        for (int ks = 0; ks < BK; ks += 8) {
            uint32_t ah[4][4], al[4][4], bh[4][2], bl[4][2];
            #pragma unroll
            for (int i = 0; i < 4; i++) {
                int row = wm * 64 + i * 16 + g;
                split_tf32(As[cur][ks + tg    ][row    ], ah[i][0], al[i][0]);
                split_tf32(As[cur][ks + tg    ][row + 8], ah[i][1], al[i][1]);
                split_tf32(As[cur][ks + tg + 4][row    ], ah[i][2], al[i][2]);
                split_tf32(As[cur][ks + tg + 4][row + 8], ah[i][3], al[i][3]);
            }
            #pragma unroll
            for (int j = 0; j < 4; j++) {
                int col = wn * 32 + j * 8 + g;
                split_tf32(Bs[cur][ks + tg    ][col], bh[j][0], bl[j][0]);
                split_tf32(Bs[cur][ks + tg + 4][col], bh[j][1], bl[j][1]);
            }
            #pragma unroll
            for (int i = 0; i < 4; i++)
                #pragma unroll
                for (int j = 0; j < 4; j++) {
                    mma_tf32(acc[i][j], al[i][0], al[i][1], al[i][2], al[i][3],
                             bh[j][0], bh[j][1]);
                    mma_tf32(acc[i][j], ah[i][0], ah[i][1], ah[i][2], ah[i][3],
                             bl[j][0], bl[j][1]);
                    mma_tf32(acc[i][j], ah[i][0], ah[i][1], ah[i][2], ah[i][3],
                             bh[j][0], bh[j][1]);
                }
        }

        // Stage next tile; single sync per iteration
        if (t + 1 < T) {
            #pragma unroll
            for (int p = 0; p < 2; p++) {
                int row = ldrow0 + p * 64;
                As[nxt][ldkv*4+0][row] = pa[p].x; As[nxt][ldkv*4+1][row] = pa[p].y;
                As[nxt][ldkv*4+2][row] = pa[p].z; As[nxt][ldkv*4+3][row] = pa[p].w;
                Bs[nxt][ldkv*4+0][row] = pb[p].x; Bs[nxt][ldkv*4+1][row] = pb[p].y;
                Bs[nxt][ldkv*4+2][row] = pb[p].z; Bs[nxt][ldkv*4+3][row] = pb[p].w;
            }
            __syncthreads();
        }
    }

    // Epilogue
    #pragma unroll
    for (int i = 0; i < 4; i++) {
        #pragma unroll
        for (int j = 0; j < 4; j++) {
            int row = bm + wm * 64 + i * 16 + g;
            int col = bn + wn * 32 + j * 8 + 2 * tg;
            float b0 = bias ? bias[col]     : 0.0f;
            float b1 = bias ? bias[col + 1] : 0.0f;
            float2 v0 = make_float2(acc[i][j][0] + b0, acc[i][j][1] + b1);
            float2 v1 = make_float2(acc[i][j][2] + b0, acc[i][j][3] + b1);
            *reinterpret_cast<float2*>(&Y[(size_t)row * N + col])       = v0;
            *reinterpret_cast<float2*>(&Y[(size_t)(row + 8) * N + col]) = v1;
        }
    }
}

// ---------------------------------------------------------------------------
// Fold Wo: Wf[e, g*D+d] = sum_{u=0..3} Wo[e, (4g+u)*D + d]
// ---------------------------------------------------------------------------
__global__ void fold_wo(const float* __restrict__ Wo, float* __restrict__ Wf)
{
    int i = blockIdx.x * blockDim.x + threadIdx.x;
    if (i >= Edim * KVdim) return;
    int e = i / KVdim;
    int c = i % KVdim;
    int gh = c / Ddim, d = c % Ddim;
    float s = 0.0f;
    #pragma unroll
    for (int u = 0; u < 4; u++)
        s += Wo[(size_t)e * KQVdim + (size_t)(gh * 4 + u) * Ddim + d];
    Wf[i] = s;
}

// ---------------------------------------------------------------------------
// Sliding-window GQA attention (flash-style), 4 distinct kv heads.
// grid: (S/32, B*HKV); block: 256 threads.
// ---------------------------------------------------------------------------
__global__ void __launch_bounds__(256, 2)
attn_window(const float* __restrict__ q, const float* __restrict__ k,
            const float* __restrict__ v, float* __restrict__ out)
{
    __shared__ float Qs[32][Ddim];
    __shared__ float Ks[Ddim][33];
    __shared__ float Vs[32][Ddim];

    const int tid  = threadIdx.x;
    const int warp = tid >> 5;
    const int lane = tid & 31;

    const int bh  = blockIdx.y;
    const int b   = bh / HKVdim;
    const int kvh = bh % HKVdim;
    const int q0  = blockIdx.x * 32;

    const float* qptr = q + ((size_t)b * Sdim + q0) * KVdim + kvh * Ddim;

    #pragma unroll
    for (int e = 0; e < 16; e++) {
        int lin = e * 256 + tid;
        int r = lin >> 7, d = lin & 127;
        Qs[r][d] = qptr[(size_t)r * KVdim + d];
    }

    float m[4], l[4], O[4][4];
    #pragma unroll
    for (int r = 0; r < 4; r++) {
        m[r] = -1e30f; l[r] = 0.0f;
        #pragma unroll
        for (int c = 0; c < 4; c++) O[r][c] = 0.0f;
    }

    int ktlo = q0 - (WIN - 1);
    if (ktlo < 0) ktlo = 0;
    ktlo = (ktlo / 32) * 32;

    for (int k0 = ktlo; k0 <= q0; k0 += 32) {
        const float* kptr = k + ((size_t)b * Sdim + k0) * KVdim + kvh * Ddim;
        const float* vptr = v + ((size_t)b * Sdim + k0) * KVdim + kvh * Ddim;
        __syncthreads();
        #pragma unroll
        for (int e = 0; e < 16; e++) {
            int lin = e * 256 + tid;
            int j = lin >> 7, d = lin & 127;
            Ks[d][j] = kptr[(size_t)j * KVdim + d];
            Vs[j][d] = vptr[(size_t)j * KVdim + d];
        }
        __syncthreads();

        #pragma unroll
        for (int r = 0; r < 4; r++) {
            const int row = warp * 4 + r;
            const int i   = q0 + row;
            const int jg  = k0 + lane;

            float s = 0.0f;
            #pragma unroll
            for (int d = 0; d < Ddim; d++)
                s = fmaf(Qs[row][d], Ks[d][lane], s);

            const bool valid = (jg <= i) && (jg > i - WIN);
            s = valid ? s : -1e30f;

            float mt = s;
            #pragma unroll
            for (int off = 16; off; off >>= 1)
                mt = fmaxf(mt, __shfl_xor_sync(0xffffffffu, mt, off));
            const float mnew  = fmaxf(m[r], mt);
            const float p     = valid ? __expf(s - mnew) : 0.0f;
            const float alpha = __expf(m[r] - mnew);
            m[r] = mnew;

            float rs = p;
            #pragma unroll
            for (int off = 16; off; off >>= 1)
                rs += __shfl_xor_sync(0xffffffffu, rs, off);
            l[r] = l[r] * alpha + rs;

            #pragma unroll
            for (int c = 0; c < 4; c++) O[r][c] *= alpha;
            #pragma unroll
            for (int j = 0; j < 32; j++) {
                const float pj = __shfl_sync(0xffffffffu, p, j);
                #pragma unroll
                for (int c = 0; c < 4; c++)
                    O[r][c] = fmaf(pj, Vs[j][c * 32 + lane], O[r][c]);
            }
        }
    }

    float* optr = out + ((size_t)b * Sdim + q0) * KVdim + kvh * Ddim;
    #pragma unroll
    for (int r = 0; r < 4; r++) {
        const int row = warp * 4 + r;
        const float inv = 1.0f / l[r];
        #pragma unroll
        for (int c = 0; c < 4; c++)
            optr[(size_t)row * KVdim + c * 32 + lane] = O[r][c] * inv;
    }
}

// ---------------------------------------------------------------------------
// Launch
// ---------------------------------------------------------------------------
extern "C" void kernel_launch(void* const* d_in, const int* in_sizes, int n_in,
                              void* d_out, int out_size)
{
    const float* x  = (const float*)d_in[0];
    const float* Wq = (const float*)d_in[1];   // only rows 0..511 used
    const float* Wk = (const float*)d_in[2];
    const float* Wv = (const float*)d_in[3];
    const float* Wo = (const float*)d_in[4];
    const float* bo = (const float*)d_in[5];
    float* out = (float*)d_out;

    float *qb, *kb, *vb, *ab, *wf;
    cudaGetSymbolAddress((void**)&qb, g_q);
    cudaGetSymbolAddress((void**)&kb, g_k);
    cudaGetSymbolAddress((void**)&vb, g_v);
    cudaGetSymbolAddress((void**)&ab, g_ao);
    cudaGetSymbolAddress((void**)&wf, g_wf);

    fold_wo<<<(Edim * KVdim + 255) / 256, 256>>>(Wo, wf);

    gemm_3xtf32<<<dim3(KVdim / BN, Mrows / BM), 256>>>(x, Wq, nullptr, qb,
                                                       Mrows, KVdim, Edim);
    gemm_3xtf32<<<dim3(KVdim / BN, Mrows / BM), 256>>>(x, Wk, nullptr, kb,
                                                       Mrows, KVdim, Edim);
    gemm_3xtf32<<<dim3(KVdim / BN, Mrows / BM), 256>>>(x, Wv, nullptr, vb,
                                                       Mrows, KVdim, Edim);

    attn_window<<<dim3(Sdim / 32, Bdim * HKVdim), 256>>>(qb, kb, vb, ab);

    gemm_3xtf32<<<dim3(Edim / BN, Mrows / BM), 256>>>(ab, wf, bo, out,
                                                      Mrows, Edim, KVdim);
}